// round 1
// baseline (speedup 1.0000x reference)
#include <cuda_runtime.h>

// Problem constants
#define MROWS 11520      // b*n = 2*5760
#define DIM   512        // d
#define HD    1960       // hidden
#define KK    7
#define SS    3
#define PP    3
#define HH    60
#define WW    108
#define LH    20
#define LW    36
#define NVECS 720        // LH*LW
#define NB2   16         // b*n / NVECS
#define NCCH  40         // HD / 49
#define PH    66         // H + 2P
#define PW    114        // W + 2P

// Scratch (device globals — no allocation allowed)
__device__ float g_h[MROWS * HD];            // h = x@W1 + b1
__device__ float g_F[NB2 * NCCH * PH * PW];  // folded padded image
__device__ float g_A[MROWS * HD];            // relu(unfold(F/norm))

// ---------------------------------------------------------------------------
// SGEMM: C[M,N] = A[M,K] @ B[K,N] + bias[N]
// 128x128 block tile, BK=8, 256 threads, 8x8 microtile per thread.
// Requires M % 128 == 0, K % 8 == 0, N % 4 == 0. Column-guarded for partial N.
// ---------------------------------------------------------------------------
__global__ __launch_bounds__(256) void sgemm_bias_kernel(
    const float* __restrict__ A, const float* __restrict__ B,
    const float* __restrict__ bias, float* __restrict__ C,
    int M, int N, int K)
{
    __shared__ float As[8][128];
    __shared__ float Bs[8][128];

    const int tid = threadIdx.x;
    const int tx = tid & 15;          // 0..15 -> column group
    const int ty = tid >> 4;          // 0..15 -> row group
    const int bm = blockIdx.y * 128;
    const int bn = blockIdx.x * 128;

    float acc[8][8];
#pragma unroll
    for (int i = 0; i < 8; i++)
#pragma unroll
        for (int j = 0; j < 8; j++) acc[i][j] = 0.0f;

    const int aRow = tid >> 1;        // 0..127
    const int aCol = (tid & 1) * 4;   // 0 or 4
    const int bRow = tid >> 5;        // 0..7
    const int bCol = (tid & 31) * 4;  // 0..124
    const int gcol = bn + bCol;

    const float* Aptr = A + (long long)(bm + aRow) * K + aCol;

    for (int k0 = 0; k0 < K; k0 += 8) {
        // Load A tile (128x8), store transposed
        float4 av = *(const float4*)(Aptr + k0);
        As[aCol + 0][aRow] = av.x;
        As[aCol + 1][aRow] = av.y;
        As[aCol + 2][aRow] = av.z;
        As[aCol + 3][aRow] = av.w;

        // Load B tile (8x128)
        float4 bv = make_float4(0.f, 0.f, 0.f, 0.f);
        if (gcol < N)
            bv = *(const float4*)(B + (long long)(k0 + bRow) * N + gcol);
        *(float4*)&Bs[bRow][bCol] = bv;

        __syncthreads();

#pragma unroll
        for (int kk = 0; kk < 8; kk++) {
            float af[8], bf[8];
            float4 a0 = *(const float4*)&As[kk][ty * 8];
            float4 a1 = *(const float4*)&As[kk][ty * 8 + 4];
            float4 b0 = *(const float4*)&Bs[kk][tx * 8];
            float4 b1 = *(const float4*)&Bs[kk][tx * 8 + 4];
            af[0]=a0.x; af[1]=a0.y; af[2]=a0.z; af[3]=a0.w;
            af[4]=a1.x; af[5]=a1.y; af[6]=a1.z; af[7]=a1.w;
            bf[0]=b0.x; bf[1]=b0.y; bf[2]=b0.z; bf[3]=b0.w;
            bf[4]=b1.x; bf[5]=b1.y; bf[6]=b1.z; bf[7]=b1.w;
#pragma unroll
            for (int i = 0; i < 8; i++)
#pragma unroll
                for (int j = 0; j < 8; j++)
                    acc[i][j] = fmaf(af[i], bf[j], acc[i][j]);
        }
        __syncthreads();
    }

    // Epilogue: + bias, store
#pragma unroll
    for (int i = 0; i < 8; i++) {
        int row = bm + ty * 8 + i;
#pragma unroll
        for (int j = 0; j < 8; j++) {
            int col = bn + tx * 8 + j;
            if (col < N)
                C[(long long)row * N + col] = acc[i][j] + bias[col];
        }
    }
}

// ---------------------------------------------------------------------------
// Fold: F[b2,cch,pr,pc] = sum over (ki,lh): ki+3lh=pr, (kj,lw): kj+3lw=pc
//       of h[(b2*20+lh)*36+lw, (cch*7+ki)*7+kj]
// Each output element gathers at most 9 inputs. No atomics.
// ---------------------------------------------------------------------------
__global__ void fold_kernel() {
    int idx = blockIdx.x * blockDim.x + threadIdx.x;
    const int total = NB2 * NCCH * PH * PW;
    if (idx >= total) return;

    int pc = idx % PW;
    int t = idx / PW;
    int pr = t % PH; t /= PH;
    int cch = t % NCCH;
    int b2 = t / NCCH;

    float s = 0.0f;
    int ki0 = pr % 3, kj0 = pc % 3;
#pragma unroll
    for (int ki = ki0; ki < KK; ki += 3) {
        int lh3 = pr - ki;
        if (lh3 < 0 || lh3 > 3 * (LH - 1)) continue;
        int lh = lh3 / 3;
#pragma unroll
        for (int kj = kj0; kj < KK; kj += 3) {
            int lw3 = pc - kj;
            if (lw3 < 0 || lw3 > 3 * (LW - 1)) continue;
            int lw = lw3 / 3;
            int tok = (b2 * LH + lh) * LW + lw;
            int ch = (cch * KK + ki) * KK + kj;
            s += g_h[(long long)tok * HD + ch];
        }
    }
    g_F[idx] = s;
}

// Overlap counts (separable): number of valid (k, l) with k + 3l == p.
__device__ __forceinline__ float inv_count(int p, int lmax3) {
    int c = 0;
#pragma unroll
    for (int k = p % 3; k < KK; k += 3) {
        int l3 = p - k;
        if (l3 >= 0 && l3 <= lmax3) c++;
    }
    return 1.0f / (float)c;
}

// ---------------------------------------------------------------------------
// Unfold + normalize + ReLU: A[m, ch] = relu(F[...]/norm) or 0 outside crop.
// ---------------------------------------------------------------------------
__global__ void unfold_relu_kernel() {
    int idx = blockIdx.x * blockDim.x + threadIdx.x;
    const int total = MROWS * HD;
    if (idx >= total) return;

    int ch = idx % HD;
    int m = idx / HD;
    int kj = ch % KK;
    int t = ch / KK;
    int ki = t % KK;
    int cch = t / KK;
    int lw = m % LW;
    t = m / LW;
    int lh = t % LH;
    int b2 = t / LH;

    int pr = ki + 3 * lh;
    int pc = kj + 3 * lw;

    float v = 0.0f;
    if (pr >= PP && pr < PP + HH && pc >= PP && pc < PP + WW) {
        float f = g_F[(((long long)(b2 * NCCH + cch)) * PH + pr) * PW + pc];
        f = fmaxf(f, 0.0f);  // relu(F/n) == relu(F)/n since n > 0
        v = f * inv_count(pr, 3 * (LH - 1)) * inv_count(pc, 3 * (LW - 1));
    }
    g_A[idx] = v;
}

// ---------------------------------------------------------------------------
extern "C" void kernel_launch(void* const* d_in, const int* in_sizes, int n_in,
                              void* d_out, int out_size) {
    const float* x  = (const float*)d_in[0];  // (2, 5760, 512)
    const float* W1 = (const float*)d_in[1];  // (512, 1960)
    const float* b1 = (const float*)d_in[2];  // (1960,)
    const float* W2 = (const float*)d_in[3];  // (1960, 512)
    const float* b2 = (const float*)d_in[4];  // (512,)
    float* out = (float*)d_out;               // (2, 5760, 512)

    float *hP = nullptr, *AP = nullptr;
    cudaGetSymbolAddress((void**)&hP, g_h);
    cudaGetSymbolAddress((void**)&AP, g_A);

    // GEMM1: h = x @ W1 + b1   (M=11520, N=1960, K=512)
    {
        dim3 grid((HD + 127) / 128, MROWS / 128);
        sgemm_bias_kernel<<<grid, 256>>>(x, W1, b1, hP, MROWS, HD, DIM);
    }

    // Fold
    {
        int total = NB2 * NCCH * PH * PW;
        fold_kernel<<<(total + 255) / 256, 256>>>();
    }

    // Unfold + normalize + ReLU
    {
        int total = MROWS * HD;
        unfold_relu_kernel<<<(total + 255) / 256, 256>>>();
    }

    // GEMM2: out = A @ W2 + b2  (M=11520, N=512, K=1960)
    {
        dim3 grid((DIM + 127) / 128, MROWS / 128);
        sgemm_bias_kernel<<<grid, 256>>>(AP, W2, b2, out, MROWS, DIM, HD);
    }
}

// round 6
// speedup vs baseline: 2.3908x; 2.3908x over previous
#include <cuda_runtime.h>
#include <cstdint>

// ---------------------------------------------------------------------------
// Problem constants
// ---------------------------------------------------------------------------
#define MROWS 11520      // b*n = 2*5760
#define DIM   512        // d
#define HD    1960       // hidden
#define KK    7
#define PP    3
#define HH    60
#define WW    108
#define LH    20
#define LW    36
#define NB2   16
#define NCCH  40
#define PH    66
#define PW    114

// Scratch (device globals — no allocation allowed)
__device__ float g_h[MROWS * HD];            // h = x@W1 + b1
__device__ float g_F[NB2 * NCCH * PH * PW];  // folded padded image
__device__ float g_A[MROWS * HD];            // relu(unfold(F/norm))
__device__ float g_W1t[HD * DIM];            // W1^T : [N=1960][K=512]
__device__ float g_W2t[DIM * HD];            // W2^T : [N=512][K=1960]

// ---------------------------------------------------------------------------
// helpers
// ---------------------------------------------------------------------------
__device__ __forceinline__ uint32_t smem_u32(const void* p) {
    uint32_t a;
    asm("{ .reg .u64 t; cvta.to.shared.u64 t, %1; cvt.u32.u64 %0, t; }"
        : "=r"(a) : "l"(p));
    return a;
}

#define LDSM_X4(r0, r1, r2, r3, a)                                            \
    asm volatile("ldmatrix.sync.aligned.m8n8.x4.shared.b16 {%0,%1,%2,%3}, [%4];" \
                 : "=r"(r0), "=r"(r1), "=r"(r2), "=r"(r3) : "r"(a))

__device__ __forceinline__ void mma_bf16(float* c, const uint32_t* a,
                                         uint32_t b0, uint32_t b1) {
    asm volatile(
        "mma.sync.aligned.m16n8k16.row.col.f32.bf16.bf16.f32 "
        "{%0,%1,%2,%3}, {%4,%5,%6,%7}, {%8,%9}, {%0,%1,%2,%3};"
        : "+f"(c[0]), "+f"(c[1]), "+f"(c[2]), "+f"(c[3])
        : "r"(a[0]), "r"(a[1]), "r"(a[2]), "r"(a[3]), "r"(b0), "r"(b1));
}

// Pack two floats to bf16x2 (v0 -> low half), return hi-parts as floats too.
__device__ __forceinline__ uint32_t pack_hi(float v0, float v1,
                                            float& h0f, float& h1f) {
    uint32_t r;
    asm("cvt.rn.bf16x2.f32 %0, %1, %2;" : "=r"(r) : "f"(v1), "f"(v0));
    h0f = __uint_as_float(r << 16);
    h1f = __uint_as_float(r & 0xffff0000u);
    return r;
}
__device__ __forceinline__ uint32_t pack_lo(float v0, float v1) {
    uint32_t r;
    asm("cvt.rn.bf16x2.f32 %0, %1, %2;" : "=r"(r) : "f"(v1), "f"(v0));
    return r;
}

// ---------------------------------------------------------------------------
// bf16x3-split MMA GEMM: C[M,N] = A[M,K] @ Bt[N,K]^T + bias[N]
// CTA tile 128x128, BK=32, 256 threads (8 warps, 2(m) x 4(n), 64x32 warp tile).
// SMEM tiles bf16, row stride 40 b16 (80 B) => conflict-free ldmatrix.
// ---------------------------------------------------------------------------
#define BSTRIDE 80                       // bytes per bf16 row (40 b16)
#define TILE_B  (128 * BSTRIDE)          // 10240 B per matrix tile
#define OFF_AH  0
#define OFF_AL  (TILE_B)
#define OFF_BH  (2 * TILE_B)
#define OFF_BL  (3 * TILE_B)
#define STAGE_B (4 * TILE_B)             // 40960 B per stage
#define SMEM_TOTAL (2 * STAGE_B)         // 81920 B

__global__ __launch_bounds__(256, 1)
void bf16x3_gemm(const float* __restrict__ A, const float* __restrict__ Bt,
                 const float* __restrict__ bias, float* __restrict__ C,
                 int M, int N, int K)
{
    extern __shared__ char smem[];
    const uint32_t sbase = smem_u32(smem);

    const int tid  = threadIdx.x;
    const int wid  = tid >> 5;
    const int lane = tid & 31;
    const int warp_m = (wid & 1) * 64;
    const int warp_n = (wid >> 1) * 32;

    const int bm = blockIdx.y * 128;
    const int bn = blockIdx.x * 128;
    const int nIter = (K + 31) / 32;

    // staging registers: 4 float4 each for A and B
    float4 ar[4], br[4];
    const int ldRow = tid >> 1;              // not used; keep structure simple

    // per-thread load coords: f4 = tid + j*256 ; row = f4>>3 ; kq = f4&7
    auto loadTile = [&](int it) {
        const int k0 = it * 32;
        const bool fullK = (k0 + 32 <= K);
#pragma unroll
        for (int j = 0; j < 4; j++) {
            int f4 = tid + j * 256;
            int row = f4 >> 3;
            int kq = f4 & 7;
            // A
            if (fullK) {
                ar[j] = *(const float4*)(A + (long long)(bm + row) * K + k0 + kq * 4);
            } else {
                float v[4];
#pragma unroll
                for (int e = 0; e < 4; e++) {
                    int kk = k0 + kq * 4 + e;
                    v[e] = (kk < K) ? A[(long long)(bm + row) * K + kk] : 0.0f;
                }
                ar[j] = make_float4(v[0], v[1], v[2], v[3]);
            }
            // B
            int ng = bn + row;
            if (fullK && ng < N) {
                br[j] = *(const float4*)(Bt + (long long)ng * K + k0 + kq * 4);
            } else {
                float v[4];
#pragma unroll
                for (int e = 0; e < 4; e++) {
                    int kk = k0 + kq * 4 + e;
                    v[e] = (ng < N && kk < K) ? Bt[(long long)ng * K + kk] : 0.0f;
                }
                br[j] = make_float4(v[0], v[1], v[2], v[3]);
            }
        }
    };

    auto storeTile = [&](int st) {
        const uint32_t stg = sbase + st * STAGE_B;
#pragma unroll
        for (int j = 0; j < 4; j++) {
            int f4 = tid + j * 256;
            int row = f4 >> 3;
            int kq = f4 & 7;
            uint32_t off = (uint32_t)(row * BSTRIDE + kq * 8);
            float h0, h1, h2, h3;
            // A
            uint32_t ah0 = pack_hi(ar[j].x, ar[j].y, h0, h1);
            uint32_t ah1 = pack_hi(ar[j].z, ar[j].w, h2, h3);
            uint32_t al0 = pack_lo(ar[j].x - h0, ar[j].y - h1);
            uint32_t al1 = pack_lo(ar[j].z - h2, ar[j].w - h3);
            asm volatile("st.shared.v2.b32 [%0], {%1,%2};" ::
                         "r"(stg + OFF_AH + off), "r"(ah0), "r"(ah1) : "memory");
            asm volatile("st.shared.v2.b32 [%0], {%1,%2};" ::
                         "r"(stg + OFF_AL + off), "r"(al0), "r"(al1) : "memory");
            // B
            uint32_t bh0 = pack_hi(br[j].x, br[j].y, h0, h1);
            uint32_t bh1 = pack_hi(br[j].z, br[j].w, h2, h3);
            uint32_t bl0 = pack_lo(br[j].x - h0, br[j].y - h1);
            uint32_t bl1 = pack_lo(br[j].z - h2, br[j].w - h3);
            asm volatile("st.shared.v2.b32 [%0], {%1,%2};" ::
                         "r"(stg + OFF_BH + off), "r"(bh0), "r"(bh1) : "memory");
            asm volatile("st.shared.v2.b32 [%0], {%1,%2};" ::
                         "r"(stg + OFF_BL + off), "r"(bl0), "r"(bl1) : "memory");
        }
    };

    float acc[4][4][4];
#pragma unroll
    for (int i = 0; i < 4; i++)
#pragma unroll
        for (int j = 0; j < 4; j++)
#pragma unroll
            for (int e = 0; e < 4; e++) acc[i][j][e] = 0.0f;

    loadTile(0);
    storeTile(0);

    for (int it = 0; it < nIter; it++) {
        __syncthreads();
        if (it + 1 < nIter) loadTile(it + 1);

        const uint32_t stg = sbase + (it & 1) * STAGE_B;
        const int rowSel = lane & 15;
        const uint32_t kHalf = ((uint32_t)(lane >> 4)) << 4;   // 0 or 16 bytes

#pragma unroll
        for (int ks = 0; ks < 2; ks++) {
            const uint32_t kb = (uint32_t)(ks * 32) + kHalf;
            uint32_t ah[4][4], al[4][4], bh[2][4], bl[2][4];
#pragma unroll
            for (int mt = 0; mt < 4; mt++) {
                uint32_t ra = (uint32_t)((warp_m + mt * 16 + rowSel) * BSTRIDE) + kb;
                LDSM_X4(ah[mt][0], ah[mt][1], ah[mt][2], ah[mt][3], stg + OFF_AH + ra);
                LDSM_X4(al[mt][0], al[mt][1], al[mt][2], al[mt][3], stg + OFF_AL + ra);
            }
#pragma unroll
            for (int ng = 0; ng < 2; ng++) {
                uint32_t rb = (uint32_t)((warp_n + ng * 16 + rowSel) * BSTRIDE) + kb;
                LDSM_X4(bh[ng][0], bh[ng][1], bh[ng][2], bh[ng][3], stg + OFF_BH + rb);
                LDSM_X4(bl[ng][0], bl[ng][1], bl[ng][2], bl[ng][3], stg + OFF_BL + rb);
            }
#pragma unroll
            for (int mt = 0; mt < 4; mt++)
#pragma unroll
                for (int ng = 0; ng < 2; ng++)
#pragma unroll
                    for (int hf = 0; hf < 2; hf++) {
                        float* c = acc[mt][ng * 2 + hf];
                        mma_bf16(c, ah[mt], bh[ng][hf], bh[ng][hf + 2]);
                        mma_bf16(c, al[mt], bh[ng][hf], bh[ng][hf + 2]);
                        mma_bf16(c, ah[mt], bl[ng][hf], bl[ng][hf + 2]);
                    }
        }

        if (it + 1 < nIter) storeTile((it + 1) & 1);
    }

    // ---- epilogue: stage accumulators through smem for coalesced stores ----
    __syncthreads();
    float* sf = (float*)smem;                 // 128 x 132 floats = 67584 B
    const int r0 = lane >> 2;
    const int c0 = (lane & 3) * 2;
#pragma unroll
    for (int mt = 0; mt < 4; mt++)
#pragma unroll
        for (int n8 = 0; n8 < 4; n8++) {
            int row = warp_m + mt * 16 + r0;
            int col = warp_n + n8 * 8 + c0;
            float* c = acc[mt][n8];
            *(float2*)&sf[row * 132 + col]       = make_float2(c[0], c[1]);
            *(float2*)&sf[(row + 8) * 132 + col] = make_float2(c[2], c[3]);
        }
    __syncthreads();

    if (bn + 128 <= N) {
#pragma unroll
        for (int t = 0; t < 16; t++) {
            int idx = tid + t * 256;          // 0..4095
            int row = idx >> 5;
            int c4 = (idx & 31) * 4;
            float4 bv = *(const float4*)(bias + bn + c4);
            float4 o;
            o.x = sf[row * 132 + c4 + 0] + bv.x;
            o.y = sf[row * 132 + c4 + 1] + bv.y;
            o.z = sf[row * 132 + c4 + 2] + bv.z;
            o.w = sf[row * 132 + c4 + 3] + bv.w;
            *(float4*)(C + (long long)(bm + row) * N + bn + c4) = o;
        }
    } else {
        for (int idx = tid; idx < 128 * 128; idx += 256) {
            int row = idx >> 7;
            int col = idx & 127;
            if (bn + col < N)
                C[(long long)(bm + row) * N + bn + col] =
                    sf[row * 132 + col] + bias[bn + col];
        }
    }
}

// ---------------------------------------------------------------------------
// Transpose: in[R][C] -> out[C][R]
// ---------------------------------------------------------------------------
__global__ void transpose_kernel(const float* __restrict__ in,
                                 float* __restrict__ out, int R, int C) {
    __shared__ float t[32][33];
    int bx = blockIdx.x * 32, by = blockIdx.y * 32;
    int x = bx + threadIdx.x;
#pragma unroll
    for (int j = threadIdx.y; j < 32; j += 8) {
        int r = by + j;
        t[j][threadIdx.x] = (r < R && x < C) ? in[(long long)r * C + x] : 0.0f;
    }
    __syncthreads();
    int xo = by + threadIdx.x;
#pragma unroll
    for (int j = threadIdx.y; j < 32; j += 8) {
        int co = bx + j;
        if (co < C && xo < R) out[(long long)co * R + xo] = t[threadIdx.x][j];
    }
}

// ---------------------------------------------------------------------------
// Fold (gather, no atomics)
// ---------------------------------------------------------------------------
__global__ void fold_kernel() {
    int idx = blockIdx.x * blockDim.x + threadIdx.x;
    const int total = NB2 * NCCH * PH * PW;
    if (idx >= total) return;

    int pc = idx % PW;
    int t = idx / PW;
    int pr = t % PH; t /= PH;
    int cch = t % NCCH;
    int b2 = t / NCCH;

    float s = 0.0f;
    int ki0 = pr % 3, kj0 = pc % 3;
#pragma unroll
    for (int ki = ki0; ki < KK; ki += 3) {
        int lh3 = pr - ki;
        if (lh3 < 0 || lh3 > 3 * (LH - 1)) continue;
        int lh = lh3 / 3;
#pragma unroll
        for (int kj = kj0; kj < KK; kj += 3) {
            int lw3 = pc - kj;
            if (lw3 < 0 || lw3 > 3 * (LW - 1)) continue;
            int lw = lw3 / 3;
            int tok = (b2 * LH + lh) * LW + lw;
            int ch = (cch * KK + ki) * KK + kj;
            s += g_h[(long long)tok * HD + ch];
        }
    }
    g_F[idx] = s;
}

__device__ __forceinline__ float inv_count(int p, int lmax3) {
    int c = 0;
#pragma unroll
    for (int k = p % 3; k < KK; k += 3) {
        int l3 = p - k;
        if (l3 >= 0 && l3 <= lmax3) c++;
    }
    return 1.0f / (float)c;
}

__global__ void unfold_relu_kernel() {
    int idx = blockIdx.x * blockDim.x + threadIdx.x;
    const int total = MROWS * HD;
    if (idx >= total) return;

    int ch = idx % HD;
    int m = idx / HD;
    int kj = ch % KK;
    int t = ch / KK;
    int ki = t % KK;
    int cch = t / KK;
    int lw = m % LW;
    t = m / LW;
    int lh = t % LH;
    int b2 = t / LH;

    int pr = ki + 3 * lh;
    int pc = kj + 3 * lw;

    float v = 0.0f;
    if (pr >= PP && pr < PP + HH && pc >= PP && pc < PP + WW) {
        float f = g_F[(((long long)(b2 * NCCH + cch)) * PH + pr) * PW + pc];
        f = fmaxf(f, 0.0f);
        v = f * inv_count(pr, 3 * (LH - 1)) * inv_count(pc, 3 * (LW - 1));
    }
    g_A[idx] = v;
}

// ---------------------------------------------------------------------------
extern "C" void kernel_launch(void* const* d_in, const int* in_sizes, int n_in,
                              void* d_out, int out_size) {
    const float* x  = (const float*)d_in[0];
    const float* W1 = (const float*)d_in[1];
    const float* b1 = (const float*)d_in[2];
    const float* W2 = (const float*)d_in[3];
    const float* b2 = (const float*)d_in[4];
    float* out = (float*)d_out;

    float *hP, *AP, *W1tP, *W2tP;
    cudaGetSymbolAddress((void**)&hP, g_h);
    cudaGetSymbolAddress((void**)&AP, g_A);
    cudaGetSymbolAddress((void**)&W1tP, g_W1t);
    cudaGetSymbolAddress((void**)&W2tP, g_W2t);

    cudaFuncSetAttribute(bf16x3_gemm, cudaFuncAttributeMaxDynamicSharedMemorySize,
                         SMEM_TOTAL);

    // Pre-transpose weights to [N][K] K-major
    {
        dim3 blk(32, 8);
        dim3 g1((HD + 31) / 32, (DIM + 31) / 32);
        transpose_kernel<<<g1, blk>>>(W1, W1tP, DIM, HD);   // -> [1960,512]
        dim3 g2((DIM + 31) / 32, (HD + 31) / 32);
        transpose_kernel<<<g2, blk>>>(W2, W2tP, HD, DIM);   // -> [512,1960]
    }

    // GEMM1: h = x @ W1 + b1   (M=11520, N=1960, K=512)
    {
        dim3 grid((HD + 127) / 128, MROWS / 128);
        bf16x3_gemm<<<grid, 256, SMEM_TOTAL>>>(x, W1tP, b1, hP, MROWS, HD, DIM);
    }

    // Fold
    {
        int total = NB2 * NCCH * PH * PW;
        fold_kernel<<<(total + 255) / 256, 256>>>();
    }

    // Unfold + normalize + ReLU
    {
        int total = MROWS * HD;
        unfold_relu_kernel<<<(total + 255) / 256, 256>>>();
    }

    // GEMM2: out = A @ W2 + b2  (M=11520, N=512, K=1960)
    {
        dim3 grid((DIM + 127) / 128, MROWS / 128);
        bf16x3_gemm<<<grid, 256, SMEM_TOTAL>>>(AP, W2tP, b2, out, MROWS, DIM, HD);
    }
}

// round 7
// speedup vs baseline: 2.9887x; 1.2501x over previous
#include <cuda_runtime.h>
#include <cuda_fp16.h>
#include <cstdint>

// ---------------------------------------------------------------------------
// Problem constants
// ---------------------------------------------------------------------------
#define MROWS 11520      // b*n = 2*5760
#define DIM   512        // d
#define HD    1960       // hidden
#define KK    7
#define PP    3
#define HH    60
#define WW    108
#define LH    20
#define LW    36
#define NB2   16
#define NCCH  40
#define PH    66
#define PW    114

// Scratch (device globals — no allocation allowed)
__device__ float g_h[MROWS * HD];            // h = x@W1 + b1
__device__ float g_F[NB2 * NCCH * PH * PW];  // folded padded image
__device__ float g_A[MROWS * HD];            // relu(unfold(F/norm))
__device__ float g_W1t[HD * DIM];            // W1^T : [N=1960][K=512]
__device__ float g_W2t[DIM * HD];            // W2^T : [N=512][K=1960]

// ---------------------------------------------------------------------------
// helpers
// ---------------------------------------------------------------------------
__device__ __forceinline__ uint32_t smem_u32(const void* p) {
    uint32_t a;
    asm("{ .reg .u64 t; cvta.to.shared.u64 t, %1; cvt.u32.u64 %0, t; }"
        : "=r"(a) : "l"(p));
    return a;
}

#define LDSM_X4(r0, r1, r2, r3, a)                                            \
    asm volatile("ldmatrix.sync.aligned.m8n8.x4.shared.b16 {%0,%1,%2,%3}, [%4];" \
                 : "=r"(r0), "=r"(r1), "=r"(r2), "=r"(r3) : "r"(a))

__device__ __forceinline__ void mma_f16(float* c, const uint32_t* a,
                                        uint32_t b0, uint32_t b1) {
    asm volatile(
        "mma.sync.aligned.m16n8k16.row.col.f32.f16.f16.f32 "
        "{%0,%1,%2,%3}, {%4,%5,%6,%7}, {%8,%9}, {%0,%1,%2,%3};"
        : "+f"(c[0]), "+f"(c[1]), "+f"(c[2]), "+f"(c[3])
        : "r"(a[0]), "r"(a[1]), "r"(a[2]), "r"(a[3]), "r"(b0), "r"(b1));
}

// pack two floats into f16x2 (v0 -> low half)
__device__ __forceinline__ uint32_t pack_f16(float v0, float v1) {
    uint32_t r;
    asm("cvt.rn.f16x2.f32 %0, %1, %2;" : "=r"(r) : "f"(v1), "f"(v0));
    return r;
}
__device__ __forceinline__ float2 unpack_f16(uint32_t r) {
    __half2 h = *reinterpret_cast<__half2*>(&r);
    return __half22float2(h);
}

// ---------------------------------------------------------------------------
// fp16 split-B MMA GEMM: C[M,N] = A[M,K] @ Bt[N,K]^T + bias[N]
//   A in fp16 (one tile); B split into hi+lo fp16 tiles (error ~2^-24 on B).
//   D = Ah*Bh + Ah*Bl = fp16(A)*B  -> rel err ~1.5e-4 (A rounding only).
// CTA tile 128x128, BK=32, 256 threads (8 warps, 2(m) x 4(n), 64x32 warp tile).
// SMEM bf16/f16 tiles, row stride 40 b16 (80 B) => conflict-free ldmatrix.
// ---------------------------------------------------------------------------
#define BSTRIDE 80                       // bytes per f16 row (40 halves)
#define TILE_B  (128 * BSTRIDE)          // 10240 B per matrix tile
#define OFF_AH  0
#define OFF_BH  (TILE_B)
#define OFF_BL  (2 * TILE_B)
#define STAGE_B (3 * TILE_B)             // 30720 B per stage
#define SMEM_TOTAL 67584                 // max(2*STAGE_B=61440, epi 128*132*4)

__global__ __launch_bounds__(256, 1)
void f16s_gemm(const float* __restrict__ A, const float* __restrict__ Bt,
               const float* __restrict__ bias, float* __restrict__ C,
               int M, int N, int K)
{
    extern __shared__ char smem[];
    const uint32_t sbase = smem_u32(smem);

    const int tid  = threadIdx.x;
    const int wid  = tid >> 5;
    const int lane = tid & 31;
    const int warp_m = (wid & 1) * 64;
    const int warp_n = (wid >> 1) * 32;

    const int bm = blockIdx.y * 128;
    const int bn = blockIdx.x * 128;
    const int nIter = (K + 31) / 32;

    float4 ar[4], br[4];

    auto loadTile = [&](int it) {
        const int k0 = it * 32;
        const bool fullK = (k0 + 32 <= K);
#pragma unroll
        for (int j = 0; j < 4; j++) {
            int f4 = tid + j * 256;
            int row = f4 >> 3;
            int kq = f4 & 7;
            if (fullK) {
                ar[j] = *(const float4*)(A + (long long)(bm + row) * K + k0 + kq * 4);
            } else {
                float v[4];
#pragma unroll
                for (int e = 0; e < 4; e++) {
                    int kk = k0 + kq * 4 + e;
                    v[e] = (kk < K) ? A[(long long)(bm + row) * K + kk] : 0.0f;
                }
                ar[j] = make_float4(v[0], v[1], v[2], v[3]);
            }
            int ng = bn + row;
            if (fullK && ng < N) {
                br[j] = *(const float4*)(Bt + (long long)ng * K + k0 + kq * 4);
            } else {
                float v[4];
#pragma unroll
                for (int e = 0; e < 4; e++) {
                    int kk = k0 + kq * 4 + e;
                    v[e] = (ng < N && kk < K) ? Bt[(long long)ng * K + kk] : 0.0f;
                }
                br[j] = make_float4(v[0], v[1], v[2], v[3]);
            }
        }
    };

    auto storeTile = [&](int st) {
        const uint32_t stg = sbase + st * STAGE_B;
#pragma unroll
        for (int j = 0; j < 4; j++) {
            int f4 = tid + j * 256;
            int row = f4 >> 3;
            int kq = f4 & 7;
            uint32_t off = (uint32_t)(row * BSTRIDE + kq * 8);
            // A: plain fp16
            uint32_t ah0 = pack_f16(ar[j].x, ar[j].y);
            uint32_t ah1 = pack_f16(ar[j].z, ar[j].w);
            asm volatile("st.shared.v2.b32 [%0], {%1,%2};" ::
                         "r"(stg + OFF_AH + off), "r"(ah0), "r"(ah1) : "memory");
            // B: hi + lo fp16
            uint32_t bh0 = pack_f16(br[j].x, br[j].y);
            uint32_t bh1 = pack_f16(br[j].z, br[j].w);
            float2 f0 = unpack_f16(bh0);
            float2 f1 = unpack_f16(bh1);
            uint32_t bl0 = pack_f16(br[j].x - f0.x, br[j].y - f0.y);
            uint32_t bl1 = pack_f16(br[j].z - f1.x, br[j].w - f1.y);
            asm volatile("st.shared.v2.b32 [%0], {%1,%2};" ::
                         "r"(stg + OFF_BH + off), "r"(bh0), "r"(bh1) : "memory");
            asm volatile("st.shared.v2.b32 [%0], {%1,%2};" ::
                         "r"(stg + OFF_BL + off), "r"(bl0), "r"(bl1) : "memory");
        }
    };

    float acc[4][4][4];
#pragma unroll
    for (int i = 0; i < 4; i++)
#pragma unroll
        for (int j = 0; j < 4; j++)
#pragma unroll
            for (int e = 0; e < 4; e++) acc[i][j][e] = 0.0f;

    loadTile(0);
    storeTile(0);

    for (int it = 0; it < nIter; it++) {
        __syncthreads();
        if (it + 1 < nIter) loadTile(it + 1);

        const uint32_t stg = sbase + (it & 1) * STAGE_B;
        const int rowSel = lane & 15;
        const uint32_t kHalf = ((uint32_t)(lane >> 4)) << 4;   // 0 or 16 B

#pragma unroll
        for (int ks = 0; ks < 2; ks++) {
            const uint32_t kb = (uint32_t)(ks * 32) + kHalf;
            uint32_t ah[4][4], bh[2][4], bl[2][4];
#pragma unroll
            for (int mt = 0; mt < 4; mt++) {
                uint32_t ra = (uint32_t)((warp_m + mt * 16 + rowSel) * BSTRIDE) + kb;
                LDSM_X4(ah[mt][0], ah[mt][1], ah[mt][2], ah[mt][3], stg + OFF_AH + ra);
            }
#pragma unroll
            for (int ng = 0; ng < 2; ng++) {
                uint32_t rb = (uint32_t)((warp_n + ng * 16 + rowSel) * BSTRIDE) + kb;
                LDSM_X4(bh[ng][0], bh[ng][1], bh[ng][2], bh[ng][3], stg + OFF_BH + rb);
                LDSM_X4(bl[ng][0], bl[ng][1], bl[ng][2], bl[ng][3], stg + OFF_BL + rb);
            }
#pragma unroll
            for (int mt = 0; mt < 4; mt++)
#pragma unroll
                for (int ng = 0; ng < 2; ng++)
#pragma unroll
                    for (int hf = 0; hf < 2; hf++) {
                        float* c = acc[mt][ng * 2 + hf];
                        mma_f16(c, ah[mt], bh[ng][hf], bh[ng][hf + 2]);
                        mma_f16(c, ah[mt], bl[ng][hf], bl[ng][hf + 2]);
                    }
        }

        if (it + 1 < nIter) storeTile((it + 1) & 1);
    }

    // ---- epilogue: stage accumulators through smem for coalesced stores ----
    __syncthreads();
    float* sf = (float*)smem;                 // 128 x 132 floats
    const int r0 = lane >> 2;
    const int c0 = (lane & 3) * 2;
#pragma unroll
    for (int mt = 0; mt < 4; mt++)
#pragma unroll
        for (int n8 = 0; n8 < 4; n8++) {
            int row = warp_m + mt * 16 + r0;
            int col = warp_n + n8 * 8 + c0;
            float* c = acc[mt][n8];
            *(float2*)&sf[row * 132 + col]       = make_float2(c[0], c[1]);
            *(float2*)&sf[(row + 8) * 132 + col] = make_float2(c[2], c[3]);
        }
    __syncthreads();

    if (bn + 128 <= N) {
#pragma unroll
        for (int t = 0; t < 16; t++) {
            int idx = tid + t * 256;
            int row = idx >> 5;
            int c4 = (idx & 31) * 4;
            float4 bv = *(const float4*)(bias + bn + c4);
            float4 o;
            o.x = sf[row * 132 + c4 + 0] + bv.x;
            o.y = sf[row * 132 + c4 + 1] + bv.y;
            o.z = sf[row * 132 + c4 + 2] + bv.z;
            o.w = sf[row * 132 + c4 + 3] + bv.w;
            *(float4*)(C + (long long)(bm + row) * N + bn + c4) = o;
        }
    } else {
        for (int idx = tid; idx < 128 * 128; idx += 256) {
            int row = idx >> 7;
            int col = idx & 127;
            if (bn + col < N)
                C[(long long)(bm + row) * N + bn + col] =
                    sf[row * 132 + col] + bias[bn + col];
        }
    }
}

// ---------------------------------------------------------------------------
// Transpose: in[R][C] -> out[C][R]
// ---------------------------------------------------------------------------
__global__ void transpose_kernel(const float* __restrict__ in,
                                 float* __restrict__ out, int R, int C) {
    __shared__ float t[32][33];
    int bx = blockIdx.x * 32, by = blockIdx.y * 32;
    int x = bx + threadIdx.x;
#pragma unroll
    for (int j = threadIdx.y; j < 32; j += 8) {
        int r = by + j;
        t[j][threadIdx.x] = (r < R && x < C) ? in[(long long)r * C + x] : 0.0f;
    }
    __syncthreads();
    int xo = by + threadIdx.x;
#pragma unroll
    for (int j = threadIdx.y; j < 32; j += 8) {
        int co = bx + j;
        if (co < C && xo < R) out[(long long)co * R + xo] = t[threadIdx.x][j];
    }
}

// ---------------------------------------------------------------------------
// Fold (gather, no atomics). One thread per (b2, pr, pc); loops all 40 cch
// with precomputed gather bases (index math amortized 40x, high MLP).
// ---------------------------------------------------------------------------
__global__ void fold_kernel() {
    int idx = blockIdx.x * blockDim.x + threadIdx.x;
    const int total = NB2 * PH * PW;        // 120384
    if (idx >= total) return;

    int pc = idx % PW;
    int t = idx / PW;
    int pr = t % PH;
    int b2 = t / PH;

    int kiv[3], lhv[3], nr = 0;
#pragma unroll
    for (int ki = pr % 3; ki < KK; ki += 3) {
        int l3 = pr - ki;
        if (l3 >= 0 && l3 <= 3 * (LH - 1)) { kiv[nr] = ki; lhv[nr] = l3 / 3; nr++; }
    }
    int kjv[3], lwv[3], nc = 0;
#pragma unroll
    for (int kj = pc % 3; kj < KK; kj += 3) {
        int l3 = pc - kj;
        if (l3 >= 0 && l3 <= 3 * (LW - 1)) { kjv[nc] = kj; lwv[nc] = l3 / 3; nc++; }
    }

    long long base9[9];
    int n9 = nr * nc;
    for (int i = 0; i < nr; i++)
        for (int j = 0; j < nc; j++) {
            int tok = (b2 * LH + lhv[i]) * LW + lwv[j];
            base9[i * nc + j] = (long long)tok * HD + kiv[i] * KK + kjv[j];
        }

    long long outIdx = (((long long)b2 * NCCH) * PH + pr) * PW + pc;
    for (int cch = 0; cch < NCCH; cch++) {
        float s = 0.0f;
        int choff = cch * (KK * KK);
        for (int q = 0; q < n9; q++) s += g_h[base9[q] + choff];
        g_F[outIdx + (long long)cch * (PH * PW)] = s;
    }
}

__device__ __forceinline__ float inv_count(int p, int lmax3) {
    int c = 0;
#pragma unroll
    for (int k = p % 3; k < KK; k += 3) {
        int l3 = p - k;
        if (l3 >= 0 && l3 <= lmax3) c++;
    }
    return 1.0f / (float)c;
}

// ---------------------------------------------------------------------------
// Unfold + normalize + ReLU: float4 per thread (HD = 1960 = 490 float4s)
// ---------------------------------------------------------------------------
__global__ void unfold_relu_kernel() {
    int idx = blockIdx.x * blockDim.x + threadIdx.x;
    const int total = MROWS * (HD / 4);
    if (idx >= total) return;

    int c4 = (idx % (HD / 4)) * 4;
    int m = idx / (HD / 4);
    int lw = m % LW;
    int t = m / LW;
    int lh = t % LH;
    int b2 = t / LH;

    const float* Fb = g_F + (long long)b2 * NCCH * PH * PW;
    float o[4];
#pragma unroll
    for (int e = 0; e < 4; e++) {
        int ch = c4 + e;
        int kj = ch % KK;
        int t2 = ch / KK;
        int ki = t2 % KK;
        int cch = t2 / KK;
        int pr = ki + 3 * lh;
        int pc = kj + 3 * lw;
        float v = 0.0f;
        if (pr >= PP && pr < PP + HH && pc >= PP && pc < PP + WW) {
            float f = Fb[((long long)cch * PH + pr) * PW + pc];
            f = fmaxf(f, 0.0f);
            v = f * inv_count(pr, 3 * (LH - 1)) * inv_count(pc, 3 * (LW - 1));
        }
        o[e] = v;
    }
    *(float4*)(g_A + (long long)m * HD + c4) = make_float4(o[0], o[1], o[2], o[3]);
}

// ---------------------------------------------------------------------------
extern "C" void kernel_launch(void* const* d_in, const int* in_sizes, int n_in,
                              void* d_out, int out_size) {
    const float* x  = (const float*)d_in[0];
    const float* W1 = (const float*)d_in[1];
    const float* b1 = (const float*)d_in[2];
    const float* W2 = (const float*)d_in[3];
    const float* b2 = (const float*)d_in[4];
    float* out = (float*)d_out;

    float *hP, *AP, *W1tP, *W2tP;
    cudaGetSymbolAddress((void**)&hP, g_h);
    cudaGetSymbolAddress((void**)&AP, g_A);
    cudaGetSymbolAddress((void**)&W1tP, g_W1t);
    cudaGetSymbolAddress((void**)&W2tP, g_W2t);

    cudaFuncSetAttribute(f16s_gemm, cudaFuncAttributeMaxDynamicSharedMemorySize,
                         SMEM_TOTAL);

    // Pre-transpose weights to [N][K] K-major
    {
        dim3 blk(32, 8);
        dim3 g1((HD + 31) / 32, (DIM + 31) / 32);
        transpose_kernel<<<g1, blk>>>(W1, W1tP, DIM, HD);   // -> [1960,512]
        dim3 g2((DIM + 31) / 32, (HD + 31) / 32);
        transpose_kernel<<<g2, blk>>>(W2, W2tP, HD, DIM);   // -> [512,1960]
    }

    // GEMM1: h = x @ W1 + b1   (M=11520, N=1960, K=512)
    {
        dim3 grid((HD + 127) / 128, MROWS / 128);
        f16s_gemm<<<grid, 256, SMEM_TOTAL>>>(x, W1tP, b1, hP, MROWS, HD, DIM);
    }

    // Fold
    {
        int total = NB2 * PH * PW;
        fold_kernel<<<(total + 255) / 256, 256>>>();
    }

    // Unfold + normalize + ReLU
    {
        int total = MROWS * (HD / 4);
        unfold_relu_kernel<<<(total + 255) / 256, 256>>>();
    }

    // GEMM2: out = A @ W2 + b2  (M=11520, N=512, K=1960)
    {
        dim3 grid((DIM + 127) / 128, MROWS / 128);
        f16s_gemm<<<grid, 256, SMEM_TOTAL>>>(AP, W2tP, b2, out, MROWS, DIM, HD);
    }
}

// round 8
// speedup vs baseline: 3.3683x; 1.1270x over previous
#include <cuda_runtime.h>
#include <cuda_fp16.h>
#include <cstdint>

// ---------------------------------------------------------------------------
// Problem constants
// ---------------------------------------------------------------------------
#define MROWS 11520      // b*n = 2*5760
#define DIM   512        // d
#define HD    1960       // hidden
#define KK    7
#define PP    3
#define HH    60
#define WW    108
#define LH    20
#define LW    36
#define NB2   16
#define NCCH  40
#define PH    66
#define PW    114

// Scratch (device globals — no allocation allowed)
__device__ float  g_h[MROWS * HD];            // h = x@W1 + b1 (fp32)
__device__ float  g_F[NB2 * NCCH * PH * PW];  // folded padded image
__device__ __half g_xh[MROWS * DIM];          // x in fp16
__device__ __half g_Ah[MROWS * HD];           // relu(unfold(F/norm)) in fp16
__device__ __half g_W1h[HD * DIM];            // fp16 hi of W1^T [N=1960][K=512]
__device__ __half g_W1l[HD * DIM];            // fp16 lo of W1^T
__device__ __half g_W2h[DIM * HD];            // fp16 hi of W2^T [N=512][K=1960]
__device__ __half g_W2l[DIM * HD];            // fp16 lo of W2^T

// ---------------------------------------------------------------------------
// helpers
// ---------------------------------------------------------------------------
__device__ __forceinline__ uint32_t smem_u32(const void* p) {
    uint32_t a;
    asm("{ .reg .u64 t; cvta.to.shared.u64 t, %1; cvt.u32.u64 %0, t; }"
        : "=r"(a) : "l"(p));
    return a;
}

#define LDSM_X4(r0, r1, r2, r3, a)                                            \
    asm volatile("ldmatrix.sync.aligned.m8n8.x4.shared.b16 {%0,%1,%2,%3}, [%4];" \
                 : "=r"(r0), "=r"(r1), "=r"(r2), "=r"(r3) : "r"(a))

__device__ __forceinline__ void mma_f16(float* c, const uint32_t* a,
                                        uint32_t b0, uint32_t b1) {
    asm volatile(
        "mma.sync.aligned.m16n8k16.row.col.f32.f16.f16.f32 "
        "{%0,%1,%2,%3}, {%4,%5,%6,%7}, {%8,%9}, {%0,%1,%2,%3};"
        : "+f"(c[0]), "+f"(c[1]), "+f"(c[2]), "+f"(c[3])
        : "r"(a[0]), "r"(a[1]), "r"(a[2]), "r"(a[3]), "r"(b0), "r"(b1));
}

#define CP_ASYNC_CG(dst, src, sz)                                             \
    asm volatile("cp.async.cg.shared.global [%0], [%1], 16, %2;"              \
                 :: "r"(dst), "l"(src), "r"(sz) : "memory")
#define CP_COMMIT() asm volatile("cp.async.commit_group;" ::: "memory")
#define CP_WAIT1()  asm volatile("cp.async.wait_group 1;" ::: "memory")
#define CP_WAIT0()  asm volatile("cp.async.wait_group 0;" ::: "memory")

// ---------------------------------------------------------------------------
// fp16 split-B MMA GEMM (all operands pre-converted fp16 in gmem):
//   C[M,N] = A[M,K] @ (Bh+Bl)[N,K]^T + bias[N]
// CTA tile 128x128, BK=32, 256 threads (8 warps, 2(m) x 4(n), 64x32 warp tile)
// cp.async double buffer; SMEM row stride 80 B => conflict-free ldmatrix.
// ---------------------------------------------------------------------------
#define BSTRIDE 80                       // bytes per row (32 halves + pad)
#define TILE_B  (128 * BSTRIDE)          // 10240 B per matrix tile
#define OFF_A   0
#define OFF_BH  (TILE_B)
#define OFF_BL  (2 * TILE_B)
#define STAGE_B (3 * TILE_B)             // 30720 B per stage
#define SMEM_TOTAL 67584                 // max(2*STAGE_B=61440, epi 128*132*4)

__global__ __launch_bounds__(256)
void f16_gemm(const __half* __restrict__ A, const __half* __restrict__ Bh,
              const __half* __restrict__ Bl, const float* __restrict__ bias,
              float* __restrict__ C, int M, int N, int K)
{
    extern __shared__ char smem[];
    const uint32_t sbase = smem_u32(smem);

    const int tid  = threadIdx.x;
    const int wid  = tid >> 5;
    const int lane = tid & 31;
    const int warp_m = (wid & 1) * 64;
    const int warp_n = (wid >> 1) * 32;

    const int bm = blockIdx.y * 128;
    const int bn = blockIdx.x * 128;
    const int nIter = (K + 31) / 32;

    // per-thread chunk coords (16B chunks): 512 chunks per tile / 256 thr = 2
    const int ch0row = tid >> 2;              // chunk j=0: rows 0..63
    const int ch0c   = tid & 3;
    const int ch1row = (tid + 256) >> 2;      // chunk j=1: rows 64..127
    const int ch1c   = ch0c;

    auto issue = [&](int it) {
        const int k0 = it * 32;
        const uint32_t stg = sbase + (uint32_t)(it & 1) * STAGE_B;
#pragma unroll
        for (int j = 0; j < 2; j++) {
            int row = j ? ch1row : ch0row;
            int c   = j ? ch1c   : ch0c;
            int kpos = k0 + c * 8;
            int rem = K - kpos;
            uint32_t abytes = rem >= 8 ? 16u : (rem > 0 ? (uint32_t)(rem * 2) : 0u);
            int ksafe = (kpos < K) ? kpos : 0;
            uint32_t doff = (uint32_t)(row * BSTRIDE + c * 16);
            const __half* asrc = A + (long long)(bm + row) * K + ksafe;
            CP_ASYNC_CG(stg + OFF_A + doff, asrc, abytes);

            int ng = bn + row;
            int srow = (ng < N) ? ng : (N - 1);
            uint32_t bbytes = (ng < N) ? abytes : 0u;
            const __half* hsrc = Bh + (long long)srow * K + ksafe;
            const __half* lsrc = Bl + (long long)srow * K + ksafe;
            CP_ASYNC_CG(stg + OFF_BH + doff, hsrc, bbytes);
            CP_ASYNC_CG(stg + OFF_BL + doff, lsrc, bbytes);
        }
        CP_COMMIT();
    };

    float acc[4][4][4];
#pragma unroll
    for (int i = 0; i < 4; i++)
#pragma unroll
        for (int j = 0; j < 4; j++)
#pragma unroll
            for (int e = 0; e < 4; e++) acc[i][j][e] = 0.0f;

    issue(0);

    const int rowSel = lane & 15;
    const uint32_t kHalf = ((uint32_t)(lane >> 4)) << 4;   // 0 or 16 B

    for (int it = 0; it < nIter; it++) {
        if (it + 1 < nIter) { issue(it + 1); CP_WAIT1(); }
        else                { CP_WAIT0(); }
        __syncthreads();

        const uint32_t stg = sbase + (uint32_t)(it & 1) * STAGE_B;
#pragma unroll
        for (int ks = 0; ks < 2; ks++) {
            const uint32_t kb = (uint32_t)(ks * 32) + kHalf;
            uint32_t ah[4][4], bh[2][4], bl[2][4];
#pragma unroll
            for (int mt = 0; mt < 4; mt++) {
                uint32_t ra = (uint32_t)((warp_m + mt * 16 + rowSel) * BSTRIDE) + kb;
                LDSM_X4(ah[mt][0], ah[mt][1], ah[mt][2], ah[mt][3], stg + OFF_A + ra);
            }
#pragma unroll
            for (int ng = 0; ng < 2; ng++) {
                uint32_t rb = (uint32_t)((warp_n + ng * 16 + rowSel) * BSTRIDE) + kb;
                LDSM_X4(bh[ng][0], bh[ng][1], bh[ng][2], bh[ng][3], stg + OFF_BH + rb);
                LDSM_X4(bl[ng][0], bl[ng][1], bl[ng][2], bl[ng][3], stg + OFF_BL + rb);
            }
#pragma unroll
            for (int mt = 0; mt < 4; mt++)
#pragma unroll
                for (int ng = 0; ng < 2; ng++)
#pragma unroll
                    for (int hf = 0; hf < 2; hf++) {
                        float* c = acc[mt][ng * 2 + hf];
                        mma_f16(c, ah[mt], bh[ng][hf], bh[ng][hf + 2]);
                        mma_f16(c, ah[mt], bl[ng][hf], bl[ng][hf + 2]);
                    }
        }
        __syncthreads();
    }

    // ---- epilogue: stage accumulators through smem for coalesced stores ----
    float* sf = (float*)smem;                 // 128 x 132 floats
    const int r0 = lane >> 2;
    const int c0 = (lane & 3) * 2;
#pragma unroll
    for (int mt = 0; mt < 4; mt++)
#pragma unroll
        for (int n8 = 0; n8 < 4; n8++) {
            int row = warp_m + mt * 16 + r0;
            int col = warp_n + n8 * 8 + c0;
            float* c = acc[mt][n8];
            *(float2*)&sf[row * 132 + col]       = make_float2(c[0], c[1]);
            *(float2*)&sf[(row + 8) * 132 + col] = make_float2(c[2], c[3]);
        }
    __syncthreads();

    if (bn + 128 <= N) {
#pragma unroll
        for (int t = 0; t < 16; t++) {
            int idx = tid + t * 256;
            int row = idx >> 5;
            int c4 = (idx & 31) * 4;
            float4 bv = *(const float4*)(bias + bn + c4);
            float4 o;
            o.x = sf[row * 132 + c4 + 0] + bv.x;
            o.y = sf[row * 132 + c4 + 1] + bv.y;
            o.z = sf[row * 132 + c4 + 2] + bv.z;
            o.w = sf[row * 132 + c4 + 3] + bv.w;
            *(float4*)(C + (long long)(bm + row) * N + bn + c4) = o;
        }
    } else {
        for (int idx = tid; idx < 128 * 128; idx += 256) {
            int row = idx >> 7;
            int col = idx & 127;
            if (bn + col < N)
                C[(long long)(bm + row) * N + bn + col] =
                    sf[row * 132 + col] + bias[bn + col];
        }
    }
}

// ---------------------------------------------------------------------------
// Transpose + fp16 hi/lo split: in[R][C] fp32 -> outh/outl[C][R] fp16
// ---------------------------------------------------------------------------
__global__ void transpose_split_kernel(const float* __restrict__ in,
                                       __half* __restrict__ outh,
                                       __half* __restrict__ outl, int R, int C) {
    __shared__ float t[32][33];
    int bx = blockIdx.x * 32, by = blockIdx.y * 32;
    int x = bx + threadIdx.x;
#pragma unroll
    for (int j = threadIdx.y; j < 32; j += 8) {
        int r = by + j;
        t[j][threadIdx.x] = (r < R && x < C) ? in[(long long)r * C + x] : 0.0f;
    }
    __syncthreads();
    int xo = by + threadIdx.x;
#pragma unroll
    for (int j = threadIdx.y; j < 32; j += 8) {
        int co = bx + j;
        if (co < C && xo < R) {
            float v = t[threadIdx.x][j];
            __half h = __float2half_rn(v);
            __half l = __float2half_rn(v - __half2float(h));
            outh[(long long)co * R + xo] = h;
            outl[(long long)co * R + xo] = l;
        }
    }
}

// ---------------------------------------------------------------------------
// fp32 -> fp16 convert (float4 granularity)
// ---------------------------------------------------------------------------
__global__ void cvt_f16_kernel(const float* __restrict__ in,
                               __half* __restrict__ out, int n4) {
    int i = blockIdx.x * blockDim.x + threadIdx.x;
    if (i >= n4) return;
    float4 v = ((const float4*)in)[i];
    __half2 a = __floats2half2_rn(v.x, v.y);
    __half2 b = __floats2half2_rn(v.z, v.w);
    ((__half2*)out)[i * 2]     = a;
    ((__half2*)out)[i * 2 + 1] = b;
}

// ---------------------------------------------------------------------------
// Fold (gather, no atomics). One thread per output element (round-6 form:
// 770k threads, issue-bound but latency-tolerant).
// ---------------------------------------------------------------------------
__global__ void fold_kernel() {
    int idx = blockIdx.x * blockDim.x + threadIdx.x;
    const int total = NB2 * NCCH * PH * PW;
    if (idx >= total) return;

    int pc = idx % PW;
    int t = idx / PW;
    int pr = t % PH; t /= PH;
    int cch = t % NCCH;
    int b2 = t / NCCH;

    float s = 0.0f;
    int ki0 = pr % 3, kj0 = pc % 3;
#pragma unroll
    for (int ki = ki0; ki < KK; ki += 3) {
        int lh3 = pr - ki;
        if (lh3 < 0 || lh3 > 3 * (LH - 1)) continue;
        int lh = lh3 / 3;
#pragma unroll
        for (int kj = kj0; kj < KK; kj += 3) {
            int lw3 = pc - kj;
            if (lw3 < 0 || lw3 > 3 * (LW - 1)) continue;
            int lw = lw3 / 3;
            int tok = (b2 * LH + lh) * LW + lw;
            int ch = (cch * KK + ki) * KK + kj;
            s += g_h[(long long)tok * HD + ch];
        }
    }
    g_F[idx] = s;
}

__device__ __forceinline__ float inv_count(int p, int lmax3) {
    int c = 0;
#pragma unroll
    for (int k = p % 3; k < KK; k += 3) {
        int l3 = p - k;
        if (l3 >= 0 && l3 <= lmax3) c++;
    }
    return 1.0f / (float)c;
}

// ---------------------------------------------------------------------------
// Unfold + normalize + ReLU -> fp16 A (4 channels / thread)
// ---------------------------------------------------------------------------
__global__ void unfold_relu_kernel() {
    int idx = blockIdx.x * blockDim.x + threadIdx.x;
    const int total = MROWS * (HD / 4);
    if (idx >= total) return;

    int c4 = (idx % (HD / 4)) * 4;
    int m = idx / (HD / 4);
    int lw = m % LW;
    int t = m / LW;
    int lh = t % LH;
    int b2 = t / LH;

    const float* Fb = g_F + (long long)b2 * NCCH * PH * PW;
    float o[4];
#pragma unroll
    for (int e = 0; e < 4; e++) {
        int ch = c4 + e;
        int kj = ch % KK;
        int t2 = ch / KK;
        int ki = t2 % KK;
        int cch = t2 / KK;
        int pr = ki + 3 * lh;
        int pc = kj + 3 * lw;
        float v = 0.0f;
        if (pr >= PP && pr < PP + HH && pc >= PP && pc < PP + WW) {
            float f = Fb[((long long)cch * PH + pr) * PW + pc];
            f = fmaxf(f, 0.0f);
            v = f * inv_count(pr, 3 * (LH - 1)) * inv_count(pc, 3 * (LW - 1));
        }
        o[e] = v;
    }
    __half2 p0 = __floats2half2_rn(o[0], o[1]);
    __half2 p1 = __floats2half2_rn(o[2], o[3]);
    __half2* dst = (__half2*)(g_Ah + (long long)m * HD + c4);
    dst[0] = p0;
    dst[1] = p1;
}

// ---------------------------------------------------------------------------
extern "C" void kernel_launch(void* const* d_in, const int* in_sizes, int n_in,
                              void* d_out, int out_size) {
    const float* x  = (const float*)d_in[0];
    const float* W1 = (const float*)d_in[1];
    const float* b1 = (const float*)d_in[2];
    const float* W2 = (const float*)d_in[3];
    const float* b2 = (const float*)d_in[4];
    float* out = (float*)d_out;

    float* hP;
    __half *xhP, *AhP, *W1hP, *W1lP, *W2hP, *W2lP;
    cudaGetSymbolAddress((void**)&hP, g_h);
    cudaGetSymbolAddress((void**)&xhP, g_xh);
    cudaGetSymbolAddress((void**)&AhP, g_Ah);
    cudaGetSymbolAddress((void**)&W1hP, g_W1h);
    cudaGetSymbolAddress((void**)&W1lP, g_W1l);
    cudaGetSymbolAddress((void**)&W2hP, g_W2h);
    cudaGetSymbolAddress((void**)&W2lP, g_W2l);

    cudaFuncSetAttribute(f16_gemm, cudaFuncAttributeMaxDynamicSharedMemorySize,
                         SMEM_TOTAL);

    // Pre-transpose + split weights to fp16 hi/lo, [N][K] K-major
    {
        dim3 blk(32, 8);
        dim3 g1((HD + 31) / 32, (DIM + 31) / 32);
        transpose_split_kernel<<<g1, blk>>>(W1, W1hP, W1lP, DIM, HD);
        dim3 g2((DIM + 31) / 32, (HD + 31) / 32);
        transpose_split_kernel<<<g2, blk>>>(W2, W2hP, W2lP, HD, DIM);
    }

    // x -> fp16
    {
        int n4 = MROWS * DIM / 4;
        cvt_f16_kernel<<<(n4 + 255) / 256, 256>>>(x, xhP, n4);
    }

    // GEMM1: h = x @ W1 + b1   (M=11520, N=1960, K=512)
    {
        dim3 grid((HD + 127) / 128, MROWS / 128);
        f16_gemm<<<grid, 256, SMEM_TOTAL>>>(xhP, W1hP, W1lP, b1, hP,
                                            MROWS, HD, DIM);
    }

    // Fold
    {
        int total = NB2 * NCCH * PH * PW;
        fold_kernel<<<(total + 255) / 256, 256>>>();
    }

    // Unfold + normalize + ReLU -> fp16
    {
        int total = MROWS * (HD / 4);
        unfold_relu_kernel<<<(total + 255) / 256, 256>>>();
    }

    // GEMM2: out = A @ W2 + b2  (M=11520, N=512, K=1960)
    {
        dim3 grid((DIM + 127) / 128, MROWS / 128);
        f16_gemm<<<grid, 256, SMEM_TOTAL>>>(AhP, W2hP, W2lP, b2, out,
                                            MROWS, DIM, HD);
    }
}

// round 12
// speedup vs baseline: 4.8281x; 1.4334x over previous
#include <cuda_runtime.h>
#include <cuda_fp16.h>
#include <cstdint>

// ---------------------------------------------------------------------------
// Problem constants
// ---------------------------------------------------------------------------
#define MROWS 11520      // b*n = 2*5760
#define DIM   512        // d
#define HD    1960       // hidden
#define KK    7
#define PP    3
#define HH    60
#define WW    108
#define LH    20
#define LW    36
#define NB2   16
#define NCCH  40
#define PH    66
#define PW    114

// Scratch (device globals — no allocation allowed)
__device__ float  g_h[MROWS * HD];            // h = x@W1 + b1 (fp32)
__device__ float  g_F[NB2 * NCCH * PH * PW];  // folded padded image
__device__ __half g_xh[MROWS * DIM];          // x in fp16
__device__ __half g_Ah[MROWS * HD];           // relu(unfold(F/norm)) in fp16
__device__ __half g_W1h[HD * DIM];            // fp16 W1^T [N=1960][K=512]
__device__ __half g_W2h[DIM * HD];            // fp16 W2^T [N=512][K=1960]

// ---------------------------------------------------------------------------
// helpers
// ---------------------------------------------------------------------------
__device__ __forceinline__ uint32_t smem_u32(const void* p) {
    uint32_t a;
    asm("{ .reg .u64 t; cvta.to.shared.u64 t, %1; cvt.u32.u64 %0, t; }"
        : "=r"(a) : "l"(p));
    return a;
}

#define LDSM_X4(r0, r1, r2, r3, a)                                            \
    asm volatile("ldmatrix.sync.aligned.m8n8.x4.shared.b16 {%0,%1,%2,%3}, [%4];" \
                 : "=r"(r0), "=r"(r1), "=r"(r2), "=r"(r3) : "r"(a))

__device__ __forceinline__ void mma_f16(float* c, const uint32_t* a,
                                        uint32_t b0, uint32_t b1) {
    asm volatile(
        "mma.sync.aligned.m16n8k16.row.col.f32.f16.f16.f32 "
        "{%0,%1,%2,%3}, {%4,%5,%6,%7}, {%8,%9}, {%0,%1,%2,%3};"
        : "+f"(c[0]), "+f"(c[1]), "+f"(c[2]), "+f"(c[3])
        : "r"(a[0]), "r"(a[1]), "r"(a[2]), "r"(a[3]), "r"(b0), "r"(b1));
}

#define CP_ASYNC_CG(dst, src, sz)                                             \
    asm volatile("cp.async.cg.shared.global [%0], [%1], 16, %2;"              \
                 :: "r"(dst), "l"(src), "r"(sz) : "memory")
#define CP_COMMIT() asm volatile("cp.async.commit_group;" ::: "memory")
#define CP_WAIT1()  asm volatile("cp.async.wait_group 1;" ::: "memory")

// ---------------------------------------------------------------------------
// fp16 MMA GEMM (operands pre-converted fp16 in gmem):
//   C[M,N] = A[M,K] @ B[N,K]^T + bias[N]
// CTA tile 128x128, BK=32, 256 threads (8 warps, 2(m) x 4(n), 64x32 warp tile)
// 3-stage cp.async pipeline, one __syncthreads per iter.
// SMEM row stride 80 B => conflict-free ldmatrix.
// ---------------------------------------------------------------------------
#define BSTRIDE 80                       // bytes per row (32 halves + pad)
#define TILE_B  (128 * BSTRIDE)          // 10240 B per matrix tile
#define OFF_A   0
#define OFF_B   (TILE_B)
#define STAGE_B (2 * TILE_B)             // 20480 B per stage
#define NSTAGE  3                        // 61440 B total stages
#define SMEM_TOTAL 67584                 // epilogue 128*132*4 dominates

__global__ __launch_bounds__(256, 2)
void f16_gemm(const __half* __restrict__ A, const __half* __restrict__ B,
              const float* __restrict__ bias, float* __restrict__ C,
              int M, int N, int K)
{
    extern __shared__ char smem[];
    const uint32_t sbase = smem_u32(smem);

    const int tid  = threadIdx.x;
    const int wid  = tid >> 5;
    const int lane = tid & 31;
    const int warp_m = (wid & 1) * 64;
    const int warp_n = (wid >> 1) * 32;

    const int bm = blockIdx.y * 128;
    const int bn = blockIdx.x * 128;
    const int nIter = (K + 31) / 32;

    // per-thread chunk coords (16B chunks): 512 chunks / 256 thr = 2 each
    const int ch0row = tid >> 2;              // rows 0..63
    const int ch0c   = tid & 3;
    const int ch1row = ch0row + 64;           // rows 64..127

    auto issue = [&](int it) {
        const int k0 = it * 32;
        const uint32_t stg = sbase + (uint32_t)(it % NSTAGE) * STAGE_B;
        const int kpos = k0 + ch0c * 8;
        const int rem = K - kpos;
        const uint32_t bytes = rem >= 8 ? 16u : (rem > 0 ? (uint32_t)(rem * 2) : 0u);
        const int ksafe = (kpos < K) ? kpos : 0;
#pragma unroll
        for (int j = 0; j < 2; j++) {
            int row = j ? ch1row : ch0row;
            uint32_t doff = (uint32_t)(row * BSTRIDE + ch0c * 16);
            const __half* asrc = A + (long long)(bm + row) * K + ksafe;
            CP_ASYNC_CG(stg + OFF_A + doff, asrc, bytes);

            int ng = bn + row;
            int srow = (ng < N) ? ng : (N - 1);
            uint32_t bbytes = (ng < N) ? bytes : 0u;
            const __half* bsrc = B + (long long)srow * K + ksafe;
            CP_ASYNC_CG(stg + OFF_B + doff, bsrc, bbytes);
        }
        CP_COMMIT();
    };

    float acc[4][4][4];
#pragma unroll
    for (int i = 0; i < 4; i++)
#pragma unroll
        for (int j = 0; j < 4; j++)
#pragma unroll
            for (int e = 0; e < 4; e++) acc[i][j][e] = 0.0f;

    issue(0);
    issue(1);
    CP_WAIT1();                 // stage 0 ready
    __syncthreads();

    const int rowSel = lane & 15;
    const uint32_t kHalf = ((uint32_t)(lane >> 4)) << 4;   // 0 or 16 B

    for (int it = 0; it < nIter; it++) {
        const uint32_t stg = sbase + (uint32_t)(it % NSTAGE) * STAGE_B;

#pragma unroll
        for (int ks = 0; ks < 2; ks++) {
            const uint32_t kb = (uint32_t)(ks * 32) + kHalf;
            uint32_t ah[4][4], bh[2][4];
#pragma unroll
            for (int mt = 0; mt < 4; mt++) {
                uint32_t ra = (uint32_t)((warp_m + mt * 16 + rowSel) * BSTRIDE) + kb;
                LDSM_X4(ah[mt][0], ah[mt][1], ah[mt][2], ah[mt][3], stg + OFF_A + ra);
            }
#pragma unroll
            for (int ng = 0; ng < 2; ng++) {
                uint32_t rb = (uint32_t)((warp_n + ng * 16 + rowSel) * BSTRIDE) + kb;
                LDSM_X4(bh[ng][0], bh[ng][1], bh[ng][2], bh[ng][3], stg + OFF_B + rb);
            }
#pragma unroll
            for (int mt = 0; mt < 4; mt++)
#pragma unroll
                for (int ng = 0; ng < 2; ng++)
#pragma unroll
                    for (int hf = 0; hf < 2; hf++)
                        mma_f16(acc[mt][ng * 2 + hf], ah[mt],
                                bh[ng][hf], bh[ng][hf + 2]);
        }

        // prefetch stage it+2 (writes stage (it-1)%3 — safe: all warps finished
        // its compute before the sync at the end of iter it-1)
        if (it + 2 < nIter) issue(it + 2);
        else                CP_COMMIT();
        CP_WAIT1();            // stage it+1 ready
        __syncthreads();
    }

    // ---- epilogue: stage accumulators through smem for coalesced stores ----
    float* sf = (float*)smem;                 // 128 x 132 floats
    const int r0 = lane >> 2;
    const int c0 = (lane & 3) * 2;
#pragma unroll
    for (int mt = 0; mt < 4; mt++)
#pragma unroll
        for (int n8 = 0; n8 < 4; n8++) {
            int row = warp_m + mt * 16 + r0;
            int col = warp_n + n8 * 8 + c0;
            float* c = acc[mt][n8];
            *(float2*)&sf[row * 132 + col]       = make_float2(c[0], c[1]);
            *(float2*)&sf[(row + 8) * 132 + col] = make_float2(c[2], c[3]);
        }
    __syncthreads();

    if (bn + 128 <= N) {
#pragma unroll
        for (int t = 0; t < 16; t++) {
            int idx = tid + t * 256;
            int row = idx >> 5;
            int c4 = (idx & 31) * 4;
            float4 bv = *(const float4*)(bias + bn + c4);
            float4 o;
            o.x = sf[row * 132 + c4 + 0] + bv.x;
            o.y = sf[row * 132 + c4 + 1] + bv.y;
            o.z = sf[row * 132 + c4 + 2] + bv.z;
            o.w = sf[row * 132 + c4 + 3] + bv.w;
            *(float4*)(C + (long long)(bm + row) * N + bn + c4) = o;
        }
    } else {
        for (int idx = tid; idx < 128 * 128; idx += 256) {
            int row = idx >> 7;
            int col = idx & 127;
            if (bn + col < N)
                C[(long long)(bm + row) * N + bn + col] =
                    sf[row * 132 + col] + bias[bn + col];
        }
    }
}

// ---------------------------------------------------------------------------
// Transpose + fp16 convert: in[R][C] fp32 -> out[C][R] fp16
// ---------------------------------------------------------------------------
__global__ void transpose_cvt_kernel(const float* __restrict__ in,
                                     __half* __restrict__ out, int R, int C) {
    __shared__ float t[32][33];
    int bx = blockIdx.x * 32, by = blockIdx.y * 32;
    int x = bx + threadIdx.x;
#pragma unroll
    for (int j = threadIdx.y; j < 32; j += 8) {
        int r = by + j;
        t[j][threadIdx.x] = (r < R && x < C) ? in[(long long)r * C + x] : 0.0f;
    }
    __syncthreads();
    int xo = by + threadIdx.x;
#pragma unroll
    for (int j = threadIdx.y; j < 32; j += 8) {
        int co = bx + j;
        if (co < C && xo < R)
            out[(long long)co * R + xo] = __float2half_rn(t[threadIdx.x][j]);
    }
}

// ---------------------------------------------------------------------------
// fp32 -> fp16 convert (float4 granularity)
// ---------------------------------------------------------------------------
__global__ void cvt_f16_kernel(const float* __restrict__ in,
                               __half* __restrict__ out, int n4) {
    int i = blockIdx.x * blockDim.x + threadIdx.x;
    if (i >= n4) return;
    float4 v = ((const float4*)in)[i];
    ((__half2*)out)[i * 2]     = __floats2half2_rn(v.x, v.y);
    ((__half2*)out)[i * 2 + 1] = __floats2half2_rn(v.z, v.w);
}

// ---------------------------------------------------------------------------
// Fold (gather, no atomics). One thread per output element.
// ---------------------------------------------------------------------------
__global__ void fold_kernel() {
    int idx = blockIdx.x * blockDim.x + threadIdx.x;
    const int total = NB2 * NCCH * PH * PW;
    if (idx >= total) return;

    int pc = idx % PW;
    int t = idx / PW;
    int pr = t % PH; t /= PH;
    int cch = t % NCCH;
    int b2 = t / NCCH;

    float s = 0.0f;
    int ki0 = pr % 3, kj0 = pc % 3;
#pragma unroll
    for (int ki = ki0; ki < KK; ki += 3) {
        int lh3 = pr - ki;
        if (lh3 < 0 || lh3 > 3 * (LH - 1)) continue;
        int lh = lh3 / 3;
#pragma unroll
        for (int kj = kj0; kj < KK; kj += 3) {
            int lw3 = pc - kj;
            if (lw3 < 0 || lw3 > 3 * (LW - 1)) continue;
            int lw = lw3 / 3;
            int tok = (b2 * LH + lh) * LW + lw;
            int ch = (cch * KK + ki) * KK + kj;
            s += g_h[(long long)tok * HD + ch];
        }
    }
    g_F[idx] = s;
}

__device__ __forceinline__ float inv_count(int p, int lmax3) {
    int c = 0;
#pragma unroll
    for (int k = p % 3; k < KK; k += 3) {
        int l3 = p - k;
        if (l3 >= 0 && l3 <= lmax3) c++;
    }
    return 1.0f / (float)c;
}

// ---------------------------------------------------------------------------
// Unfold + normalize + ReLU -> fp16 A (4 channels / thread)
// ---------------------------------------------------------------------------
__global__ void unfold_relu_kernel() {
    int idx = blockIdx.x * blockDim.x + threadIdx.x;
    const int total = MROWS * (HD / 4);
    if (idx >= total) return;

    int c4 = (idx % (HD / 4)) * 4;
    int m = idx / (HD / 4);
    int lw = m % LW;
    int t = m / LW;
    int lh = t % LH;
    int b2 = t / LH;

    const float* Fb = g_F + (long long)b2 * NCCH * PH * PW;
    float o[4];
#pragma unroll
    for (int e = 0; e < 4; e++) {
        int ch = c4 + e;
        int kj = ch % KK;
        int t2 = ch / KK;
        int ki = t2 % KK;
        int cch = t2 / KK;
        int pr = ki + 3 * lh;
        int pc = kj + 3 * lw;
        float v = 0.0f;
        if (pr >= PP && pr < PP + HH && pc >= PP && pc < PP + WW) {
            float f = Fb[((long long)cch * PH + pr) * PW + pc];
            f = fmaxf(f, 0.0f);
            v = f * inv_count(pr, 3 * (LH - 1)) * inv_count(pc, 3 * (LW - 1));
        }
        o[e] = v;
    }
    __half2 p0 = __floats2half2_rn(o[0], o[1]);
    __half2 p1 = __floats2half2_rn(o[2], o[3]);
    __half2* dst = (__half2*)(g_Ah + (long long)m * HD + c4);
    dst[0] = p0;
    dst[1] = p1;
}

// ---------------------------------------------------------------------------
extern "C" void kernel_launch(void* const* d_in, const int* in_sizes, int n_in,
                              void* d_out, int out_size) {
    const float* x  = (const float*)d_in[0];
    const float* W1 = (const float*)d_in[1];
    const float* b1 = (const float*)d_in[2];
    const float* W2 = (const float*)d_in[3];
    const float* b2 = (const float*)d_in[4];
    float* out = (float*)d_out;

    float* hP;
    __half *xhP, *AhP, *W1hP, *W2hP;
    cudaGetSymbolAddress((void**)&hP, g_h);
    cudaGetSymbolAddress((void**)&xhP, g_xh);
    cudaGetSymbolAddress((void**)&AhP, g_Ah);
    cudaGetSymbolAddress((void**)&W1hP, g_W1h);
    cudaGetSymbolAddress((void**)&W2hP, g_W2h);

    cudaFuncSetAttribute(f16_gemm, cudaFuncAttributeMaxDynamicSharedMemorySize,
                         SMEM_TOTAL);

    // Pre-transpose + convert weights to fp16, [N][K] K-major
    {
        dim3 blk(32, 8);
        dim3 g1((HD + 31) / 32, (DIM + 31) / 32);
        transpose_cvt_kernel<<<g1, blk>>>(W1, W1hP, DIM, HD);
        dim3 g2((DIM + 31) / 32, (HD + 31) / 32);
        transpose_cvt_kernel<<<g2, blk>>>(W2, W2hP, HD, DIM);
    }

    // x -> fp16
    {
        int n4 = MROWS * DIM / 4;
        cvt_f16_kernel<<<(n4 + 255) / 256, 256>>>(x, xhP, n4);
    }

    // GEMM1: h = x @ W1 + b1   (M=11520, N=1960, K=512)
    {
        dim3 grid((HD + 127) / 128, MROWS / 128);
        f16_gemm<<<grid, 256, SMEM_TOTAL>>>(xhP, W1hP, b1, hP, MROWS, HD, DIM);
    }

    // Fold
    {
        int total = NB2 * NCCH * PH * PW;
        fold_kernel<<<(total + 255) / 256, 256>>>();
    }

    // Unfold + normalize + ReLU -> fp16
    {
        int total = MROWS * (HD / 4);
        unfold_relu_kernel<<<(total + 255) / 256, 256>>>();
    }

    // GEMM2: out = A @ W2 + b2  (M=11520, N=512, K=1960)
    {
        dim3 grid((DIM + 127) / 128, MROWS / 128);
        f16_gemm<<<grid, 256, SMEM_TOTAL>>>(AhP, W2hP, b2, out, MROWS, DIM, HD);
    }
}